// round 14
// baseline (speedup 1.0000x reference)
#include <cuda_runtime.h>

#define N 512
#define D 256
#define KSPLIT 8

// Scratch (device globals — no allocation allowed)
__device__ float g_q[N * N];
__device__ float g_k[N * N];
__device__ float g_v[N * N];
__device__ float g_s[N * N];
__device__ float g_sp[KSPLIT][N * N];   // split-K partials of q@k
__device__ float g_op[KSPLIT][N * N];   // split-K partials of s@v

#define PROJ_BLOCKS 1184   // 148 * 8 (persistent single wave)

__device__ __forceinline__ float dot4(float4 a, float4 b) {
    return a.x * b.x + a.y * b.y + a.z * b.z + a.w * b.w;
}

// Packed fp32x2 FMA (sm_103a FFMA2 — PTX-only)
__device__ __forceinline__ void ffma2(unsigned long long& d,
                                      unsigned long long a,
                                      unsigned long long b) {
    asm("fma.rn.f32x2 %0, %1, %2, %0;" : "+l"(d) : "l"(a), "l"(b));
}
__device__ __forceinline__ unsigned long long bcast2(float x) {
    unsigned long long r;
    asm("mov.b64 %0, {%1, %1};" : "=l"(r) : "f"(x));
    return r;
}
__device__ __forceinline__ void unpack2(unsigned long long v, float& lo, float& hi) {
    asm("mov.b64 {%0, %1}, %2;" : "=f"(lo), "=f"(hi) : "l"(v));
}

// ---------------------------------------------------------------------------
// Kernel 1: fused rank-1 projections — best measured config (6.8 TB/s,
// at the LTS/HBM streaming ceiling).
// ---------------------------------------------------------------------------
__global__ void __launch_bounds__(256) proj_kernel(
    const float* __restrict__ xq, const float* __restrict__ xk,
    const float* __restrict__ xv, const float* __restrict__ WQ,
    const float* __restrict__ WK, const float* __restrict__ WV)
{
    __shared__ float sW[3][D];
    int tid = threadIdx.x;
    sW[0][tid] = WQ[tid];
    sW[1][tid] = WK[tid];
    sW[2][tid] = WV[tid];
    __syncthreads();

    const int warp = tid >> 5;
    const int lane = tid & 31;
    const long long stride = (long long)PROJ_BLOCKS * 8;
    const long long total = 3LL * N * N;

    for (long long row = (long long)blockIdx.x * 8 + warp; row < total; row += stride) {
        int t = (int)(row >> 18);
        int r = (int)(row & (N * N - 1));

        const float* x = (t == 0) ? xq : (t == 1) ? xk : xv;
        const float4* xr = reinterpret_cast<const float4*>(x + (size_t)r * D);
        const float4* w4 = reinterpret_cast<const float4*>(sW[t]);

        float4 a0 = __ldcs(&xr[lane]);
        float4 a1 = __ldcs(&xr[lane + 32]);
        float4 b0 = w4[lane];
        float4 b1 = w4[lane + 32];

        float acc = dot4(a0, b0) + dot4(a1, b1);

#pragma unroll
        for (int o = 16; o > 0; o >>= 1)
            acc += __shfl_xor_sync(0xffffffffu, acc, o);

        if (lane == 0) {
            float* g = (t == 0) ? g_q : (t == 1) ? g_k : g_v;
            g[r] = acc;
        }
    }
}

// ---------------------------------------------------------------------------
// Kernel 2/4: split-K SGEMM partials, FFMA2, occupancy-tuned.
// BM=64, BN=64, BK=32; 256 threads; 4x4 microtile as 2x4 f32x2 pairs
// (~64 regs -> 4 blocks/SM, 32 warps/SM). grid (8,8,KSPLIT)=512 blocks.
// As rows permuted [0,2,1,3] per 4-row group so one ld.shared.v2.b64
// yields pairs (r0,r2),(r1,r3) directly.
// ---------------------------------------------------------------------------
__global__ void __launch_bounds__(256, 4) sgemm_kernel(int mode)
{
    const float* __restrict__ A = (mode == 0) ? g_q : g_s;
    const float* __restrict__ B = (mode == 0) ? g_k : g_v;
    float* __restrict__ C = (mode == 0) ? g_sp[blockIdx.z] : g_op[blockIdx.z];

    __shared__ float As[32][72];    // [k][perm(m)], pad 8 -> 288B rows (16B-aligned)
    __shared__ float Bs[32][64];    // [k][n]

    const int bx = blockIdx.x * 64;
    const int by = blockIdx.y * 64;
    const int kbase = blockIdx.z * (N / KSPLIT);
    const int tid = threadIdx.x;
    const int tx = tid & 15;                      // n micro (16*4 = 64)
    const int ty = tid >> 4;                      // m micro (16*4 = 64)

    // Global load assignments
    const int am = tid >> 2;                      // A row 0..63 (4 thr/row)
    const int pmr = (am & ~3) | ((am & 1) << 1) | ((am >> 1) & 1);  // perm slot
    const int ak = (tid & 3) * 8;                 // A k offset (2 float4)
    const int bn = (tid & 15) * 4;                // B n, float4
    const int bk = tid >> 4;                      // B k; +16 for 2nd

    // Prefetch first tile
    float4 aR0 = *(const float4*)&A[(by + am) * N + kbase + ak];
    float4 aR1 = *(const float4*)&A[(by + am) * N + kbase + ak + 4];
    float4 b0 = *(const float4*)&B[(kbase + bk) * N + bx + bn];
    float4 b1 = *(const float4*)&B[(kbase + bk + 16) * N + bx + bn];

    unsigned long long accp[2][4];
#pragma unroll
    for (int p = 0; p < 2; p++)
#pragma unroll
        for (int j = 0; j < 4; j++)
            accp[p][j] = 0ULL;

    for (int k0 = 0; k0 < N / KSPLIT; k0 += 32) {
        // Commit prefetched tile (A transposed to [k][perm(m)])
        As[ak + 0][pmr] = aR0.x;
        As[ak + 1][pmr] = aR0.y;
        As[ak + 2][pmr] = aR0.z;
        As[ak + 3][pmr] = aR0.w;
        As[ak + 4][pmr] = aR1.x;
        As[ak + 5][pmr] = aR1.y;
        As[ak + 6][pmr] = aR1.z;
        As[ak + 7][pmr] = aR1.w;
        *(float4*)&Bs[bk][bn]      = b0;
        *(float4*)&Bs[bk + 16][bn] = b1;
        __syncthreads();

        if (k0 + 32 < N / KSPLIT) {
            int kn = kbase + k0 + 32;
            aR0 = *(const float4*)&A[(by + am) * N + kn + ak];
            aR1 = *(const float4*)&A[(by + am) * N + kn + ak + 4];
            b0 = *(const float4*)&B[(kn + bk) * N + bx + bn];
            b1 = *(const float4*)&B[(kn + bk + 16) * N + bx + bn];
        }

#pragma unroll
        for (int kk = 0; kk < 32; kk++) {
            // A pairs: (r0,r2),(r1,r3) of this thread's 4 rows
            ulonglong2 ap = *(const ulonglong2*)&As[kk][ty * 4];
            float4 bq = *(const float4*)&Bs[kk][tx * 4];

            unsigned long long a2[2] = { ap.x, ap.y };
            unsigned long long b2[4] = { bcast2(bq.x), bcast2(bq.y),
                                         bcast2(bq.z), bcast2(bq.w) };
#pragma unroll
            for (int p = 0; p < 2; p++)
#pragma unroll
                for (int j = 0; j < 4; j++)
                    ffma2(accp[p][j], a2[p], b2[j]);
        }
        __syncthreads();
    }

    // Epilogue: pair0 = rows (ty*4+0, ty*4+2), pair1 = rows (ty*4+1, ty*4+3)
    float lo0[4], hi0[4], lo1[4], hi1[4];
#pragma unroll
    for (int j = 0; j < 4; j++) {
        unpack2(accp[0][j], lo0[j], hi0[j]);
        unpack2(accp[1][j], lo1[j], hi1[j]);
    }
    *(float4*)&C[(by + ty * 4 + 0) * N + bx + tx * 4] = make_float4(lo0[0], lo0[1], lo0[2], lo0[3]);
    *(float4*)&C[(by + ty * 4 + 1) * N + bx + tx * 4] = make_float4(lo1[0], lo1[1], lo1[2], lo1[3]);
    *(float4*)&C[(by + ty * 4 + 2) * N + bx + tx * 4] = make_float4(hi0[0], hi0[1], hi0[2], hi0[3]);
    *(float4*)&C[(by + ty * 4 + 3) * N + bx + tx * 4] = make_float4(hi1[0], hi1[1], hi1[2], hi1[3]);
}

// ---------------------------------------------------------------------------
// Kernel 3: sum KSPLIT s-partials + row softmax -> g_s.
// ---------------------------------------------------------------------------
__global__ void __launch_bounds__(256) softmax_kernel()
{
    __shared__ float smax[2][4];
    __shared__ float ssum[2][4];

    const int tid = threadIdx.x;
    const int half = tid >> 7;
    const int t = tid & 127;
    const int warp = (tid >> 5) & 3;
    const int lane = tid & 31;
    const int row = blockIdx.x * 2 + half;
    const size_t off = (size_t)row * N + t * 4;

    float4 a = make_float4(0.f, 0.f, 0.f, 0.f);
#pragma unroll
    for (int z = 0; z < KSPLIT; z++) {
        float4 p = *(const float4*)&g_sp[z][off];
        a.x += p.x; a.y += p.y; a.z += p.z; a.w += p.w;
    }

    float mx = fmaxf(fmaxf(a.x, a.y), fmaxf(a.z, a.w));
#pragma unroll
    for (int o = 16; o > 0; o >>= 1)
        mx = fmaxf(mx, __shfl_xor_sync(0xffffffffu, mx, o));
    if (lane == 0) smax[half][warp] = mx;
    __syncthreads();
    mx = fmaxf(fmaxf(smax[half][0], smax[half][1]),
               fmaxf(smax[half][2], smax[half][3]));

    float4 e;
    e.x = __expf(a.x - mx);
    e.y = __expf(a.y - mx);
    e.z = __expf(a.z - mx);
    e.w = __expf(a.w - mx);

    float s = e.x + e.y + e.z + e.w;
#pragma unroll
    for (int o = 16; o > 0; o >>= 1)
        s += __shfl_xor_sync(0xffffffffu, s, o);
    if (lane == 0) ssum[half][warp] = s;
    __syncthreads();
    float inv = 1.0f / (ssum[half][0] + ssum[half][1] + ssum[half][2] + ssum[half][3]);

    e.x *= inv; e.y *= inv; e.z *= inv; e.w *= inv;
    *(float4*)&g_s[off] = e;
}

// ---------------------------------------------------------------------------
// Kernel 5: sum KSPLIT out-partials -> d_out.
// ---------------------------------------------------------------------------
__global__ void __launch_bounds__(256) reduce_out_kernel(float* __restrict__ out)
{
    int i = blockIdx.x * 256 + threadIdx.x;
    float4 r = ((const float4*)g_op[0])[i];
#pragma unroll
    for (int z = 1; z < KSPLIT; z++) {
        float4 s = ((const float4*)g_op[z])[i];
        r.x += s.x; r.y += s.y; r.z += s.z; r.w += s.w;
    }
    ((float4*)out)[i] = r;
}

// ---------------------------------------------------------------------------
extern "C" void kernel_launch(void* const* d_in, const int* in_sizes, int n_in,
                              void* d_out, int out_size)
{
    const float* xq = (const float*)d_in[0];
    const float* xk = (const float*)d_in[1];
    const float* xv = (const float*)d_in[2];
    const float* WQ = (const float*)d_in[3];
    const float* WK = (const float*)d_in[4];
    const float* WV = (const float*)d_in[5];
    float* out = (float*)d_out;

    proj_kernel<<<PROJ_BLOCKS, 256>>>(xq, xk, xv, WQ, WK, WV);

    dim3 gg(N / 64, N / 64, KSPLIT);   // (8, 8, 8) = 512 blocks
    sgemm_kernel<<<gg, 256>>>(0);

    softmax_kernel<<<N / 2, 256>>>();

    sgemm_kernel<<<gg, 256>>>(1);

    reduce_out_kernel<<<(N * N / 4) / 256, 256>>>(out);
}

// round 15
// speedup vs baseline: 1.0437x; 1.0437x over previous
#include <cuda_runtime.h>
#include <cuda_bf16.h>

#define N 512
#define D 256
#define KSPLIT 8

// Scratch (device globals — no allocation allowed)
__device__ float g_k[N * N];
__device__ float g_v[N * N];
__device__ float g_sp[KSPLIT][N * N];   // split-K partials of q@k
__device__ float g_op[KSPLIT][N * N];   // split-K partials of s@v

// bf16 hi/lo split operands for the tensor-core GEMMs
__device__ __align__(16) __nv_bfloat16 qh[N * N], ql[N * N];    // q  [m][k]
__device__ __align__(16) __nv_bfloat16 kht[N * N], klt[N * N];  // k^T [n][k]
__device__ __align__(16) __nv_bfloat16 sh_[N * N], sl_[N * N];  // s  [m][k]
__device__ __align__(16) __nv_bfloat16 vht[N * N], vlt[N * N];  // v^T [n][k]

#define PROJ_BLOCKS 1184   // 148 * 8 (persistent single wave)

__device__ __forceinline__ float dot4(float4 a, float4 b) {
    return a.x * b.x + a.y * b.y + a.z * b.z + a.w * b.w;
}

// m16n8k16 bf16 MMA, fp32 accumulate (row-major A, col-major B)
__device__ __forceinline__ void mma16816(float* c, const unsigned* a,
                                         unsigned b0, unsigned b1) {
    asm volatile(
        "mma.sync.aligned.m16n8k16.row.col.f32.bf16.bf16.f32 "
        "{%0,%1,%2,%3}, {%4,%5,%6,%7}, {%8,%9}, {%0,%1,%2,%3};"
        : "+f"(c[0]), "+f"(c[1]), "+f"(c[2]), "+f"(c[3])
        : "r"(a[0]), "r"(a[1]), "r"(a[2]), "r"(a[3]), "r"(b0), "r"(b1));
}

// ---------------------------------------------------------------------------
// Kernel 1: fused rank-1 projections (LTS-capped config, 6.8 TB/s).
// q is written directly as bf16 hi/lo split; k,v stay fp32 for transposing.
// ---------------------------------------------------------------------------
__global__ void __launch_bounds__(256) proj_kernel(
    const float* __restrict__ xq, const float* __restrict__ xk,
    const float* __restrict__ xv, const float* __restrict__ WQ,
    const float* __restrict__ WK, const float* __restrict__ WV)
{
    __shared__ float sW[3][D];
    int tid = threadIdx.x;
    sW[0][tid] = WQ[tid];
    sW[1][tid] = WK[tid];
    sW[2][tid] = WV[tid];
    __syncthreads();

    const int warp = tid >> 5;
    const int lane = tid & 31;
    const long long stride = (long long)PROJ_BLOCKS * 8;
    const long long total = 3LL * N * N;

    for (long long row = (long long)blockIdx.x * 8 + warp; row < total; row += stride) {
        int t = (int)(row >> 18);
        int r = (int)(row & (N * N - 1));

        const float* x = (t == 0) ? xq : (t == 1) ? xk : xv;
        const float4* xr = reinterpret_cast<const float4*>(x + (size_t)r * D);
        const float4* w4 = reinterpret_cast<const float4*>(sW[t]);

        float4 a0 = __ldcs(&xr[lane]);
        float4 a1 = __ldcs(&xr[lane + 32]);
        float4 b0 = w4[lane];
        float4 b1 = w4[lane + 32];

        float acc = dot4(a0, b0) + dot4(a1, b1);

#pragma unroll
        for (int o = 16; o > 0; o >>= 1)
            acc += __shfl_xor_sync(0xffffffffu, acc, o);

        if (lane == 0) {
            if (t == 0) {
                __nv_bfloat16 h = __float2bfloat16(acc);
                qh[r] = h;
                ql[r] = __float2bfloat16(acc - __bfloat162float(h));
            } else if (t == 1) {
                g_k[r] = acc;
            } else {
                g_v[r] = acc;
            }
        }
    }
}

// ---------------------------------------------------------------------------
// Kernel 2: transpose + bf16 hi/lo split. out[j][i] = split(in[i][j]).
// mode 0: g_k -> kht/klt ; mode 1: g_v -> vht/vlt. grid (16,16), 256 thr.
// ---------------------------------------------------------------------------
__global__ void __launch_bounds__(256) tsplit_kernel(int mode)
{
    const float* __restrict__ in = (mode == 0) ? g_k : g_v;
    __nv_bfloat16* __restrict__ oh = (mode == 0) ? kht : vht;
    __nv_bfloat16* __restrict__ ol = (mode == 0) ? klt : vlt;

    __shared__ float t[32][33];
    const int bi = blockIdx.x * 32;   // input row base
    const int bj = blockIdx.y * 32;   // input col base
    const int tx = threadIdx.x & 31;
    const int ty = threadIdx.x >> 5;  // 0..7

#pragma unroll
    for (int r = 0; r < 4; r++)
        t[ty + r * 8][tx] = in[(size_t)(bi + ty + r * 8) * N + bj + tx];
    __syncthreads();

#pragma unroll
    for (int r = 0; r < 4; r++) {
        float v = t[tx][ty + r * 8];
        __nv_bfloat16 h = __float2bfloat16(v);
        __nv_bfloat16 l = __float2bfloat16(v - __bfloat162float(h));
        size_t o = (size_t)(bj + ty + r * 8) * N + bi + tx;
        oh[o] = h;
        ol[o] = l;
    }
}

// ---------------------------------------------------------------------------
// Kernel 3/5: tensor-core GEMM partials, 3xBF16 error-compensated.
// C_part[z] = Ah@Bh^T + Ah@Bl^T + Al@Bh^T over a 64-wide K slice.
// Block tile 64m x 64n; 8 warps (4m x 2n); warp tile 16m x 32n.
// grid (8 n, 8 m, KSPLIT) = 512 blocks.
// mode 0: A=q(hi/lo), B=k^T -> g_sp ; mode 1: A=s, B=v^T -> g_op.
// ---------------------------------------------------------------------------
__global__ void __launch_bounds__(256, 2) mma_gemm_kernel(int mode)
{
    const __nv_bfloat16* __restrict__ Ah = (mode == 0) ? qh : sh_;
    const __nv_bfloat16* __restrict__ Al = (mode == 0) ? ql : sl_;
    const __nv_bfloat16* __restrict__ Bh = (mode == 0) ? kht : vht;
    const __nv_bfloat16* __restrict__ Bl = (mode == 0) ? klt : vlt;
    float* __restrict__ C = (mode == 0) ? g_sp[blockIdx.z] : g_op[blockIdx.z];

    // +8 bf16 pad: 144B row stride (16B-aligned, conflict-free frag loads)
    __shared__ __align__(16) __nv_bfloat16 sAh[64][72], sAl[64][72];
    __shared__ __align__(16) __nv_bfloat16 sBh[64][72], sBl[64][72];

    const int bx = blockIdx.x * 64;   // n
    const int by = blockIdx.y * 64;   // m
    const int kb = blockIdx.z * 64;   // K slice

    const int tid = threadIdx.x;
    const int lane = tid & 31;
    const int warp = tid >> 5;
    const int wm = warp >> 1;         // 0..3 -> m offset wm*16
    const int wn = warp & 1;          // 0..1 -> n offset wn*32
    const int gid = lane >> 2;        // groupID 0..7
    const int tig = lane & 3;         // thread-in-group

    // Load 4 tiles of 64x64 bf16 (each 512 uint4; 2 per thread)
#pragma unroll
    for (int i = 0; i < 2; i++) {
        int idx = tid + i * 256;
        int r = idx >> 3;
        int c = (idx & 7) * 8;
        *(uint4*)&sAh[r][c] = *(const uint4*)&Ah[(size_t)(by + r) * N + kb + c];
        *(uint4*)&sAl[r][c] = *(const uint4*)&Al[(size_t)(by + r) * N + kb + c];
        *(uint4*)&sBh[r][c] = *(const uint4*)&Bh[(size_t)(bx + r) * N + kb + c];
        *(uint4*)&sBl[r][c] = *(const uint4*)&Bl[(size_t)(bx + r) * N + kb + c];
    }
    __syncthreads();

    float acc[4][4] = {};   // [ni][c-frag]

#pragma unroll
    for (int ks = 0; ks < 4; ks++) {
        const int k0 = ks * 16;

        // A fragments (m16k16): a0 row=gid col=tig*2; a1 row+8; a2 col+8; a3 both
        unsigned aH[4], aL[4];
        {
            int ar = wm * 16 + gid;
            int ac = k0 + tig * 2;
            aH[0] = *(const unsigned*)&sAh[ar][ac];
            aH[1] = *(const unsigned*)&sAh[ar + 8][ac];
            aH[2] = *(const unsigned*)&sAh[ar][ac + 8];
            aH[3] = *(const unsigned*)&sAh[ar + 8][ac + 8];
            aL[0] = *(const unsigned*)&sAl[ar][ac];
            aL[1] = *(const unsigned*)&sAl[ar + 8][ac];
            aL[2] = *(const unsigned*)&sAl[ar][ac + 8];
            aL[3] = *(const unsigned*)&sAl[ar + 8][ac + 8];
        }

#pragma unroll
        for (int ni = 0; ni < 4; ni++) {
            // B fragments (k16n8, col-major): b0 k=tig*2 n=gid; b1 k+8
            int br = wn * 32 + ni * 8 + gid;
            int bc = k0 + tig * 2;
            unsigned bh0 = *(const unsigned*)&sBh[br][bc];
            unsigned bh1 = *(const unsigned*)&sBh[br][bc + 8];
            unsigned bl0 = *(const unsigned*)&sBl[br][bc];
            unsigned bl1 = *(const unsigned*)&sBl[br][bc + 8];

            mma16816(acc[ni], aH, bh0, bh1);   // hi*hi
            mma16816(acc[ni], aH, bl0, bl1);   // hi*lo
            mma16816(acc[ni], aL, bh0, bh1);   // lo*hi
        }
    }

    // Epilogue: c0,c1 row=gid col=tig*2,+1 ; c2,c3 row+8
#pragma unroll
    for (int ni = 0; ni < 4; ni++) {
        int row = by + wm * 16 + gid;
        int col = bx + wn * 32 + ni * 8 + tig * 2;
        *(float2*)&C[(size_t)row * N + col] = make_float2(acc[ni][0], acc[ni][1]);
        *(float2*)&C[(size_t)(row + 8) * N + col] = make_float2(acc[ni][2], acc[ni][3]);
    }
}

// ---------------------------------------------------------------------------
// Kernel 4: sum KSPLIT s-partials + row softmax -> sh_/sl_ (bf16 split).
// ---------------------------------------------------------------------------
__global__ void __launch_bounds__(256) softmax_kernel()
{
    __shared__ float smax[2][4];
    __shared__ float ssum[2][4];

    const int tid = threadIdx.x;
    const int half = tid >> 7;
    const int t = tid & 127;
    const int warp = (tid >> 5) & 3;
    const int lane = tid & 31;
    const int row = blockIdx.x * 2 + half;
    const size_t off = (size_t)row * N + t * 4;

    float4 a = make_float4(0.f, 0.f, 0.f, 0.f);
#pragma unroll
    for (int z = 0; z < KSPLIT; z++) {
        float4 p = *(const float4*)&g_sp[z][off];
        a.x += p.x; a.y += p.y; a.z += p.z; a.w += p.w;
    }

    float mx = fmaxf(fmaxf(a.x, a.y), fmaxf(a.z, a.w));
#pragma unroll
    for (int o = 16; o > 0; o >>= 1)
        mx = fmaxf(mx, __shfl_xor_sync(0xffffffffu, mx, o));
    if (lane == 0) smax[half][warp] = mx;
    __syncthreads();
    mx = fmaxf(fmaxf(smax[half][0], smax[half][1]),
               fmaxf(smax[half][2], smax[half][3]));

    float4 e;
    e.x = __expf(a.x - mx);
    e.y = __expf(a.y - mx);
    e.z = __expf(a.z - mx);
    e.w = __expf(a.w - mx);

    float s = e.x + e.y + e.z + e.w;
#pragma unroll
    for (int o = 16; o > 0; o >>= 1)
        s += __shfl_xor_sync(0xffffffffu, s, o);
    if (lane == 0) ssum[half][warp] = s;
    __syncthreads();
    float inv = 1.0f / (ssum[half][0] + ssum[half][1] + ssum[half][2] + ssum[half][3]);

    float v[4] = { e.x * inv, e.y * inv, e.z * inv, e.w * inv };
#pragma unroll
    for (int j = 0; j < 4; j++) {
        __nv_bfloat16 h = __float2bfloat16(v[j]);
        sh_[off + j] = h;
        sl_[off + j] = __float2bfloat16(v[j] - __bfloat162float(h));
    }
}

// ---------------------------------------------------------------------------
// Kernel 6: sum KSPLIT out-partials -> d_out.
// ---------------------------------------------------------------------------
__global__ void __launch_bounds__(256) reduce_out_kernel(float* __restrict__ out)
{
    int i = blockIdx.x * 256 + threadIdx.x;
    float4 r = ((const float4*)g_op[0])[i];
#pragma unroll
    for (int z = 1; z < KSPLIT; z++) {
        float4 s = ((const float4*)g_op[z])[i];
        r.x += s.x; r.y += s.y; r.z += s.z; r.w += s.w;
    }
    ((float4*)out)[i] = r;
}

// ---------------------------------------------------------------------------
extern "C" void kernel_launch(void* const* d_in, const int* in_sizes, int n_in,
                              void* d_out, int out_size)
{
    const float* xq = (const float*)d_in[0];
    const float* xk = (const float*)d_in[1];
    const float* xv = (const float*)d_in[2];
    const float* WQ = (const float*)d_in[3];
    const float* WK = (const float*)d_in[4];
    const float* WV = (const float*)d_in[5];
    float* out = (float*)d_out;

    // 1) projections (q emitted as bf16 hi/lo; k,v fp32)
    proj_kernel<<<PROJ_BLOCKS, 256>>>(xq, xk, xv, WQ, WK, WV);

    // 2) transpose+split k and v for the tensor GEMM B operands
    dim3 tg(16, 16);
    tsplit_kernel<<<tg, 256>>>(0);
    tsplit_kernel<<<tg, 256>>>(1);

    // 3) y partials = q @ k (3xBF16 tensor cores, split-K)
    dim3 gg(N / 64, N / 64, KSPLIT);   // (8,8,8) = 512 blocks
    mma_gemm_kernel<<<gg, 256>>>(0);

    // 4) softmax (emits s as bf16 hi/lo)
    softmax_kernel<<<N / 2, 256>>>();

    // 5) out partials = s @ v
    mma_gemm_kernel<<<gg, 256>>>(1);

    // 6) sum partials -> out
    reduce_out_kernel<<<(N * N / 4) / 256, 256>>>(out);
}